// round 7
// baseline (speedup 1.0000x reference)
#include <cuda_runtime.h>

#define BB     16
#define CC     512
#define SS     1024
#define HEADS  8
#define DH     64
#define INNER  512     // HEADS*DH
#define N3     1536    // 3*INNER
#define ATT_SCALE 0.125f  // 64^-0.5

// Scratch (static device globals — allocation-free per harness rules)
__device__ float g_qkv[(size_t)BB * SS * N3];    // [b][s][h*192 + {q,k,v}]
__device__ float g_res[(size_t)BB * SS * INNER]; // [b][s][h*64+d]

// tf32 round-to-nearest (keeps value in a float container)
__device__ __forceinline__ float tf32r(float f) {
    unsigned u;
    asm("cvt.rna.tf32.f32 %0, %1;" : "=r"(u) : "f"(f));
    return __uint_as_float(u);
}
__device__ __forceinline__ float4 tf32r4(float4 v) {
    return make_float4(tf32r(v.x), tf32r(v.y), tf32r(v.z), tf32r(v.w));
}

// m16n8k8 tf32 MMA, fp32 accumulate (D == C)
__device__ __forceinline__ void mma_tf32(float* d, const float* a, const float* b) {
    asm volatile(
        "mma.sync.aligned.m16n8k8.row.col.f32.tf32.tf32.f32 "
        "{%0,%1,%2,%3}, {%4,%5,%6,%7}, {%8,%9}, {%0,%1,%2,%3};\n"
        : "+f"(d[0]), "+f"(d[1]), "+f"(d[2]), "+f"(d[3])
        : "r"(__float_as_uint(a[0])), "r"(__float_as_uint(a[1])),
          "r"(__float_as_uint(a[2])), "r"(__float_as_uint(a[3])),
          "r"(__float_as_uint(b[0])), "r"(__float_as_uint(b[1])));
}

// FMA/ALU-only exp (no MUFU). Valid for x <= ~0 (softmax deltas); clamped.
// rel err ~2e-6. ~10 instructions, all fixed-latency pipes.
__device__ __forceinline__ float fexp(float x) {
    x = fmaxf(x, -80.0f);
    // t = x*log2(e); round via magic constant 1.5*2^23
    float tm = fmaf(x, 1.44269504088896f, 12582912.0f);
    float i  = tm - 12582912.0f;                 // rint(x*log2e)
    float f  = fmaf(x, 1.44269504088896f, -i);   // frac in [-0.5, 0.5]
    float g  = f * 0.69314718055995f;            // |g| <= 0.347
    float p  = fmaf(g, 0.008333333333f, 0.041666666666f);  // 1/120, 1/24
    p = fmaf(p, g, 0.166666666666f);
    p = fmaf(p, g, 0.5f);
    p = fmaf(p, g, 1.0f);
    p = fmaf(p, g, 1.0f);
    // scale by 2^i: exponent-stuff (bits(tm)<<23) + bits(1.0f)
    float s = __int_as_float((__float_as_int(tm) << 23) + 0x3F800000);
    return p * s;
}

// ---------------------------------------------------------------------------
// Kernel 1: qkv = xs @ W_proj + b_proj, xs[b][s][c] = x[b][c][s]
// 128x128 block tile, tf32 mma.sync, warp tile 64x32, double-buffered smem.
// ---------------------------------------------------------------------------
__global__ __launch_bounds__(256, 2) void qkv_gemm_k(
    const float* __restrict__ x, const float* __restrict__ Wp,
    const float* __restrict__ bp)
{
    __shared__ float sA[2][16][132];   // [buf][k][m]  (tf32-rounded)
    __shared__ float sB[2][16][132];   // [buf][k][n]  (tf32-rounded)
    const int n0 = blockIdx.x * 128;
    const int m0 = blockIdx.y * 128;
    const int b  = m0 >> 10;
    const int s0 = m0 & (SS - 1);
    const int tid = threadIdx.x;
    const int lk = tid >> 4, lm4 = (tid & 15) << 2;
    const int warp = tid >> 5, lane = tid & 31;
    const int wm = warp & 1, wn = warp >> 1;       // 2 x 4 warp grid
    const int gid = lane >> 2, tig = lane & 3;

    float4 av0, av1, bv0, bv1;
    {
        const size_t arow = ((size_t)(b * CC + lk)) * SS + s0 + lm4;
        const size_t brow = (size_t)lk * N3 + n0 + lm4;
        av0 = *(const float4*)&x[arow];
        av1 = *(const float4*)&x[arow + 64];
        bv0 = *(const float4*)&Wp[brow];
        bv1 = *(const float4*)&Wp[brow + 64];
    }
    *(float4*)&sA[0][lk][lm4]      = tf32r4(av0);
    *(float4*)&sA[0][lk][lm4 + 64] = tf32r4(av1);
    *(float4*)&sB[0][lk][lm4]      = tf32r4(bv0);
    *(float4*)&sB[0][lk][lm4 + 64] = tf32r4(bv1);
    __syncthreads();

    float acc[4][4][4] = {};   // [mf][nf][reg]

    for (int k0 = 0; k0 < CC; k0 += 16) {
        const int buf = (k0 >> 4) & 1;
        const bool more = (k0 + 16) < CC;
        if (more) {
            const size_t arow = ((size_t)(b * CC + k0 + 16 + lk)) * SS + s0 + lm4;
            const size_t brow = (size_t)(k0 + 16 + lk) * N3 + n0 + lm4;
            av0 = *(const float4*)&x[arow];
            av1 = *(const float4*)&x[arow + 64];
            bv0 = *(const float4*)&Wp[brow];
            bv1 = *(const float4*)&Wp[brow + 64];
        }
        #pragma unroll
        for (int ks = 0; ks < 16; ks += 8) {
            float afr[4][4], bfr[4][2];
            #pragma unroll
            for (int mf = 0; mf < 4; mf++) {
                const int m = wm * 64 + mf * 16 + gid;
                afr[mf][0] = sA[buf][ks + tig][m];
                afr[mf][1] = sA[buf][ks + tig][m + 8];
                afr[mf][2] = sA[buf][ks + tig + 4][m];
                afr[mf][3] = sA[buf][ks + tig + 4][m + 8];
            }
            #pragma unroll
            for (int nf = 0; nf < 4; nf++) {
                const int n = wn * 32 + nf * 8 + gid;
                bfr[nf][0] = sB[buf][ks + tig][n];
                bfr[nf][1] = sB[buf][ks + tig + 4][n];
            }
            #pragma unroll
            for (int mf = 0; mf < 4; mf++)
                #pragma unroll
                for (int nf = 0; nf < 4; nf++)
                    mma_tf32(acc[mf][nf], afr[mf], bfr[nf]);
        }
        if (more) {
            const int nb = buf ^ 1;
            *(float4*)&sA[nb][lk][lm4]      = tf32r4(av0);
            *(float4*)&sA[nb][lk][lm4 + 64] = tf32r4(av1);
            *(float4*)&sB[nb][lk][lm4]      = tf32r4(bv0);
            *(float4*)&sB[nb][lk][lm4 + 64] = tf32r4(bv1);
            __syncthreads();
        }
    }

    #pragma unroll
    for (int mf = 0; mf < 4; mf++) {
        const int rowa = m0 + wm * 64 + mf * 16 + gid;
        const int rowb = rowa + 8;
        #pragma unroll
        for (int nf = 0; nf < 4; nf++) {
            const int col = n0 + wn * 32 + nf * 8 + tig * 2;
            const float2 bias = *(const float2*)&bp[col];
            float2 oa = make_float2(acc[mf][nf][0] + bias.x, acc[mf][nf][1] + bias.y);
            float2 ob = make_float2(acc[mf][nf][2] + bias.x, acc[mf][nf][3] + bias.y);
            *(float2*)&g_qkv[(size_t)rowa * N3 + col] = oa;
            *(float2*)&g_qkv[(size_t)rowb * N3 + col] = ob;
        }
    }
}

// ---------------------------------------------------------------------------
// Kernel 2: flash attention (fp32 matmuls, FMA-pipe exp).
// ---------------------------------------------------------------------------
__global__ __launch_bounds__(256, 2) void attn_k()
{
    extern __shared__ float sm[];
    float* sQt = sm;                  // [64][128] Q^T (scaled, swizzled)
    float* sKt = sQt + 64 * 128;      // [64][64]  K^T (swizzled)
    float* sV  = sKt + 64 * 64;       // [64][68]
    float* sP  = sV + 64 * 68;        // [128][68]
    float4* sQtv = (float4*)sQt;      // row stride 32
    float4* sKtv = (float4*)sKt;      // row stride 16
    float4* sVv  = (float4*)sV;       // row stride 17
    float4* sPv  = (float4*)sP;       // row stride 17

    const int bh = blockIdx.y;
    const int b = bh >> 3, h = bh & 7;
    const int q0 = blockIdx.x * 128;
    const int tid = threadIdx.x;
    const int tx = tid & 15, ty = tid >> 4;

    const float* qbase = g_qkv + (size_t)b * SS * N3 + h * (3 * DH);

    #pragma unroll
    for (int it = 0; it < 2; it++) {
        int idx = tid + it * 256;
        int d4g = idx & 15, rg = idx >> 4;
        int d4 = d4g << 2, i0 = rg << 2;
        float4 m0 = *(const float4*)&qbase[(size_t)(q0 + i0 + 0) * N3 + d4];
        float4 m1 = *(const float4*)&qbase[(size_t)(q0 + i0 + 1) * N3 + d4];
        float4 m2 = *(const float4*)&qbase[(size_t)(q0 + i0 + 2) * N3 + d4];
        float4 m3 = *(const float4*)&qbase[(size_t)(q0 + i0 + 3) * N3 + d4];
        int phys = (rg & 16) | ((rg & 15) ^ d4g);
        sQtv[(d4 + 0) * 32 + phys] = make_float4(m0.x * ATT_SCALE, m1.x * ATT_SCALE,
                                                 m2.x * ATT_SCALE, m3.x * ATT_SCALE);
        sQtv[(d4 + 1) * 32 + phys] = make_float4(m0.y * ATT_SCALE, m1.y * ATT_SCALE,
                                                 m2.y * ATT_SCALE, m3.y * ATT_SCALE);
        sQtv[(d4 + 2) * 32 + phys] = make_float4(m0.z * ATT_SCALE, m1.z * ATT_SCALE,
                                                 m2.z * ATT_SCALE, m3.z * ATT_SCALE);
        sQtv[(d4 + 3) * 32 + phys] = make_float4(m0.w * ATT_SCALE, m1.w * ATT_SCALE,
                                                 m2.w * ATT_SCALE, m3.w * ATT_SCALE);
    }

    float m_i[8], l_i[8], o[8][4] = {};
    #pragma unroll
    for (int r = 0; r < 8; r++) { m_i[r] = -1e30f; l_i[r] = 0.f; }

    const int kd4g = tid & 15, krg = tid >> 4;
    const int kd4 = kd4g << 2, kj0 = krg << 2;
    const int kphys = krg ^ kd4g;

    float4 kreg[4], vreg[4];
    #pragma unroll
    for (int r = 0; r < 4; r++)
        kreg[r] = *(const float4*)&qbase[(size_t)(kj0 + r) * N3 + DH + kd4];
    #pragma unroll
    for (int it = 0; it < 4; it++) {
        int idx = tid + it * 256;
        int j = idx >> 4, c4 = (idx & 15) << 2;
        vreg[it] = *(const float4*)&qbase[(size_t)j * N3 + 2 * DH + c4];
    }

    for (int kt = 0; kt < 16; kt++) {
        __syncthreads();
        sKtv[(kd4 + 0) * 16 + kphys] = make_float4(kreg[0].x, kreg[1].x, kreg[2].x, kreg[3].x);
        sKtv[(kd4 + 1) * 16 + kphys] = make_float4(kreg[0].y, kreg[1].y, kreg[2].y, kreg[3].y);
        sKtv[(kd4 + 2) * 16 + kphys] = make_float4(kreg[0].z, kreg[1].z, kreg[2].z, kreg[3].z);
        sKtv[(kd4 + 3) * 16 + kphys] = make_float4(kreg[0].w, kreg[1].w, kreg[2].w, kreg[3].w);
        #pragma unroll
        for (int it = 0; it < 4; it++) {
            int idx = tid + it * 256;
            int j = idx >> 4, c4g = idx & 15;
            sVv[j * 17 + c4g] = vreg[it];
        }
        __syncthreads();

        if (kt + 1 < 16) {
            const int k0n = (kt + 1) * 64;
            #pragma unroll
            for (int r = 0; r < 4; r++)
                kreg[r] = *(const float4*)&qbase[(size_t)(k0n + kj0 + r) * N3 + DH + kd4];
        }

        float sf[8][4] = {};
        #pragma unroll
        for (int dg = 0; dg < 16; dg++) {
            const int pa = ty ^ dg;
            const int pb = tx ^ dg;
            #pragma unroll
            for (int dd = 0; dd < 4; dd++) {
                const int d = dg * 4 + dd;
                float4 a0 = sQtv[d * 32 + pa];
                float4 a1 = sQtv[d * 32 + 16 + pa];
                float4 b0 = sKtv[d * 16 + pb];
                float a[8] = {a0.x, a0.y, a0.z, a0.w, a1.x, a1.y, a1.z, a1.w};
                float bq[4] = {b0.x, b0.y, b0.z, b0.w};
                #pragma unroll
                for (int r = 0; r < 8; r++)
                    #pragma unroll
                    for (int c = 0; c < 4; c++)
                        sf[r][c] = fmaf(a[r], bq[c], sf[r][c]);
            }
        }

        #pragma unroll
        for (int r = 0; r < 8; r++) {
            const int qrow = (r < 4) ? (ty * 4 + r) : (64 + ty * 4 + r - 4);
            float mx = fmaxf(fmaxf(sf[r][0], sf[r][1]), fmaxf(sf[r][2], sf[r][3]));
            #pragma unroll
            for (int off = 8; off >= 1; off >>= 1)
                mx = fmaxf(mx, __shfl_xor_sync(0xffffffffu, mx, off));
            float m_new = fmaxf(m_i[r], mx);
            float p0 = fexp(sf[r][0] - m_new);
            float p1 = fexp(sf[r][1] - m_new);
            float p2 = fexp(sf[r][2] - m_new);
            float p3 = fexp(sf[r][3] - m_new);
            sPv[qrow * 17 + tx] = make_float4(p0, p1, p2, p3);
            float rs = (p0 + p1) + (p2 + p3);
            #pragma unroll
            for (int off = 8; off >= 1; off >>= 1)
                rs += __shfl_xor_sync(0xffffffffu, rs, off);
            float alpha = fexp(m_i[r] - m_new);
            l_i[r] = l_i[r] * alpha + rs;
            m_i[r] = m_new;
            #pragma unroll
            for (int c = 0; c < 4; c++) o[r][c] *= alpha;
        }
        __syncwarp();

        if (kt + 1 < 16) {
            const int k0n = (kt + 1) * 64;
            #pragma unroll
            for (int it = 0; it < 4; it++) {
                int idx = tid + it * 256;
                int j = idx >> 4, c4 = (idx & 15) << 2;
                vreg[it] = *(const float4*)&qbase[(size_t)(k0n + j) * N3 + 2 * DH + c4];
            }
        }

        #pragma unroll
        for (int j4 = 0; j4 < 16; j4++) {
            float4 b0 = sVv[(j4 * 4 + 0) * 17 + tx];
            float4 b1 = sVv[(j4 * 4 + 1) * 17 + tx];
            float4 b2 = sVv[(j4 * 4 + 2) * 17 + tx];
            float4 b3 = sVv[(j4 * 4 + 3) * 17 + tx];
            #pragma unroll
            for (int half = 0; half < 2; half++) {
                #pragma unroll
                for (int r = 0; r < 4; r++) {
                    float4 av = sPv[((half ? 64 : 0) + ty * 4 + r) * 17 + j4];
                    const int ro = half * 4 + r;
                    o[ro][0] = fmaf(av.x, b0.x, o[ro][0]);
                    o[ro][1] = fmaf(av.x, b0.y, o[ro][1]);
                    o[ro][2] = fmaf(av.x, b0.z, o[ro][2]);
                    o[ro][3] = fmaf(av.x, b0.w, o[ro][3]);
                    o[ro][0] = fmaf(av.y, b1.x, o[ro][0]);
                    o[ro][1] = fmaf(av.y, b1.y, o[ro][1]);
                    o[ro][2] = fmaf(av.y, b1.z, o[ro][2]);
                    o[ro][3] = fmaf(av.y, b1.w, o[ro][3]);
                    o[ro][0] = fmaf(av.z, b2.x, o[ro][0]);
                    o[ro][1] = fmaf(av.z, b2.y, o[ro][1]);
                    o[ro][2] = fmaf(av.z, b2.z, o[ro][2]);
                    o[ro][3] = fmaf(av.z, b2.w, o[ro][3]);
                    o[ro][0] = fmaf(av.w, b3.x, o[ro][0]);
                    o[ro][1] = fmaf(av.w, b3.y, o[ro][1]);
                    o[ro][2] = fmaf(av.w, b3.z, o[ro][2]);
                    o[ro][3] = fmaf(av.w, b3.w, o[ro][3]);
                }
            }
        }
    }

    float* rbase = g_res + ((size_t)b * SS + q0) * INNER + h * DH;
    #pragma unroll
    for (int r = 0; r < 8; r++) {
        const int qrow = (r < 4) ? (ty * 4 + r) : (64 + ty * 4 + r - 4);
        float inv = 1.f / l_i[r];
        float4 ov;
        ov.x = o[r][0] * inv; ov.y = o[r][1] * inv;
        ov.z = o[r][2] * inv; ov.w = o[r][3] * inv;
        *(float4*)&rbase[(size_t)qrow * INNER + tx * 4] = ov;
    }
}

// ---------------------------------------------------------------------------
// Kernel 3: out[b][c][s] = res @ W_out + b_out + x. tf32 mma.sync,
// 128(c) x 128(s) block tile, warp tile 64x32, double-buffered.
// ---------------------------------------------------------------------------
__global__ __launch_bounds__(256, 2) void out_gemm_k(
    const float* __restrict__ x, const float* __restrict__ Wo,
    const float* __restrict__ bo, float* __restrict__ out)
{
    __shared__ float sA[2][16][132];   // [buf][k][c]  (tf32)
    __shared__ float sB[2][16][132];   // [buf][k][s]  (tf32)
    const int s0 = blockIdx.x * 128;
    const int c0 = blockIdx.y * 128;
    const int b  = blockIdx.z;
    const int tid = threadIdx.x;
    const int lk = tid >> 4, lc4 = (tid & 15) << 2;
    const int ls = tid >> 1, lkb = (tid & 1) << 3;
    const int warp = tid >> 5, lane = tid & 31;
    const int wm = warp & 1, wn = warp >> 1;
    const int gid = lane >> 2, tig = lane & 3;

    float4 av0, av1, bv0, bv1;
    {
        const size_t arow = (size_t)lk * CC + c0 + lc4;
        av0 = *(const float4*)&Wo[arow];
        av1 = *(const float4*)&Wo[arow + 64];
        const size_t brow = ((size_t)(b * SS + s0 + ls)) * INNER + lkb;
        bv0 = *(const float4*)&g_res[brow];
        bv1 = *(const float4*)&g_res[brow + 4];
    }
    *(float4*)&sA[0][lk][lc4]      = tf32r4(av0);
    *(float4*)&sA[0][lk][lc4 + 64] = tf32r4(av1);
    sB[0][lkb + 0][ls] = tf32r(bv0.x); sB[0][lkb + 1][ls] = tf32r(bv0.y);
    sB[0][lkb + 2][ls] = tf32r(bv0.z); sB[0][lkb + 3][ls] = tf32r(bv0.w);
    sB[0][lkb + 4][ls] = tf32r(bv1.x); sB[0][lkb + 5][ls] = tf32r(bv1.y);
    sB[0][lkb + 6][ls] = tf32r(bv1.z); sB[0][lkb + 7][ls] = tf32r(bv1.w);
    __syncthreads();

    float acc[4][4][4] = {};

    for (int k0 = 0; k0 < INNER; k0 += 16) {
        const int buf = (k0 >> 4) & 1;
        const bool more = (k0 + 16) < INNER;
        if (more) {
            const size_t arow = (size_t)(k0 + 16 + lk) * CC + c0 + lc4;
            av0 = *(const float4*)&Wo[arow];
            av1 = *(const float4*)&Wo[arow + 64];
            const size_t brow = ((size_t)(b * SS + s0 + ls)) * INNER + k0 + 16 + lkb;
            bv0 = *(const float4*)&g_res[brow];
            bv1 = *(const float4*)&g_res[brow + 4];
        }
        #pragma unroll
        for (int ks = 0; ks < 16; ks += 8) {
            float afr[4][4], bfr[4][2];
            #pragma unroll
            for (int mf = 0; mf < 4; mf++) {
                const int m = wm * 64 + mf * 16 + gid;
                afr[mf][0] = sA[buf][ks + tig][m];
                afr[mf][1] = sA[buf][ks + tig][m + 8];
                afr[mf][2] = sA[buf][ks + tig + 4][m];
                afr[mf][3] = sA[buf][ks + tig + 4][m + 8];
            }
            #pragma unroll
            for (int nf = 0; nf < 4; nf++) {
                const int n = wn * 32 + nf * 8 + gid;
                bfr[nf][0] = sB[buf][ks + tig][n];
                bfr[nf][1] = sB[buf][ks + tig + 4][n];
            }
            #pragma unroll
            for (int mf = 0; mf < 4; mf++)
                #pragma unroll
                for (int nf = 0; nf < 4; nf++)
                    mma_tf32(acc[mf][nf], afr[mf], bfr[nf]);
        }
        if (more) {
            const int nb = buf ^ 1;
            *(float4*)&sA[nb][lk][lc4]      = tf32r4(av0);
            *(float4*)&sA[nb][lk][lc4 + 64] = tf32r4(av1);
            sB[nb][lkb + 0][ls] = tf32r(bv0.x); sB[nb][lkb + 1][ls] = tf32r(bv0.y);
            sB[nb][lkb + 2][ls] = tf32r(bv0.z); sB[nb][lkb + 3][ls] = tf32r(bv0.w);
            sB[nb][lkb + 4][ls] = tf32r(bv1.x); sB[nb][lkb + 5][ls] = tf32r(bv1.y);
            sB[nb][lkb + 6][ls] = tf32r(bv1.z); sB[nb][lkb + 7][ls] = tf32r(bv1.w);
            __syncthreads();
        }
    }

    #pragma unroll
    for (int mf = 0; mf < 4; mf++) {
        const int ca = c0 + wm * 64 + mf * 16 + gid;
        const int cb = ca + 8;
        const float biasa = bo[ca];
        const float biasb = bo[cb];
        #pragma unroll
        for (int nf = 0; nf < 4; nf++) {
            const int s = s0 + wn * 32 + nf * 8 + tig * 2;
            const size_t basea = ((size_t)(b * CC + ca)) * SS + s;
            const size_t baseb = ((size_t)(b * CC + cb)) * SS + s;
            float2 xva = *(const float2*)&x[basea];
            float2 xvb = *(const float2*)&x[baseb];
            float2 oa = make_float2(acc[mf][nf][0] + biasa + xva.x,
                                    acc[mf][nf][1] + biasa + xva.y);
            float2 ob = make_float2(acc[mf][nf][2] + biasb + xvb.x,
                                    acc[mf][nf][3] + biasb + xvb.y);
            *(float2*)&out[basea] = oa;
            *(float2*)&out[baseb] = ob;
        }
    }
}

// ---------------------------------------------------------------------------
extern "C" void kernel_launch(void* const* d_in, const int* in_sizes, int n_in,
                              void* d_out, int out_size)
{
    const float* x  = (const float*)d_in[0];
    const float* Wp = (const float*)d_in[1];
    const float* bp = (const float*)d_in[2];
    const float* Wo = (const float*)d_in[3];
    const float* bo = (const float*)d_in[4];
    float* out = (float*)d_out;

    const int attn_smem = (64 * 128 + 64 * 64 + 64 * 68 + 128 * 68) * 4; // 101376
    cudaFuncSetAttribute(attn_k, cudaFuncAttributeMaxDynamicSharedMemorySize,
                         attn_smem);

    dim3 g1(N3 / 128, (BB * SS) / 128);        // 12 x 128
    qkv_gemm_k<<<g1, 256>>>(x, Wp, bp);

    dim3 g2(SS / 128, BB * HEADS);             // 8 x 128
    attn_k<<<g2, 256, attn_smem>>>();

    dim3 g3(SS / 128, CC / 128, BB);           // 8 x 4 x 16
    out_gemm_k<<<g3, 256>>>(x, Wo, bo, out);
}

// round 8
// speedup vs baseline: 1.7585x; 1.7585x over previous
#include <cuda_runtime.h>

#define BB     16
#define CC     512
#define SS     1024
#define HEADS  8
#define DH     64
#define INNER  512     // HEADS*DH
#define N3     1536    // 3*INNER
#define ATT_SCALE 0.125f  // 64^-0.5
#define STR    72      // attn smem row stride (72 mod 32 == 8)

// Scratch (static device globals — allocation-free per harness rules)
__device__ float g_qkv[(size_t)BB * SS * N3];    // [b][s][h*192 + {q,k,v}]
__device__ float g_res[(size_t)BB * SS * INNER]; // [b][s][h*64+d]

// tf32 round-to-nearest (keeps value in a float container)
__device__ __forceinline__ float tf32r(float f) {
    unsigned u;
    asm("cvt.rna.tf32.f32 %0, %1;" : "=r"(u) : "f"(f));
    return __uint_as_float(u);
}
__device__ __forceinline__ float4 tf32r4(float4 v) {
    return make_float4(tf32r(v.x), tf32r(v.y), tf32r(v.z), tf32r(v.w));
}

// m16n8k8 tf32 MMA, fp32 accumulate (D == C)
__device__ __forceinline__ void mma_tf32(float* d, const float* a, const float* b) {
    asm volatile(
        "mma.sync.aligned.m16n8k8.row.col.f32.tf32.tf32.f32 "
        "{%0,%1,%2,%3}, {%4,%5,%6,%7}, {%8,%9}, {%0,%1,%2,%3};\n"
        : "+f"(d[0]), "+f"(d[1]), "+f"(d[2]), "+f"(d[3])
        : "r"(__float_as_uint(a[0])), "r"(__float_as_uint(a[1])),
          "r"(__float_as_uint(a[2])), "r"(__float_as_uint(a[3])),
          "r"(__float_as_uint(b[0])), "r"(__float_as_uint(b[1])));
}

// ---------------------------------------------------------------------------
// Kernel 1: qkv = xs @ W_proj + b_proj (tf32 mma.sync, unchanged from R6)
// ---------------------------------------------------------------------------
__global__ __launch_bounds__(256, 2) void qkv_gemm_k(
    const float* __restrict__ x, const float* __restrict__ Wp,
    const float* __restrict__ bp)
{
    __shared__ float sA[2][16][132];
    __shared__ float sB[2][16][132];
    const int n0 = blockIdx.x * 128;
    const int m0 = blockIdx.y * 128;
    const int b  = m0 >> 10;
    const int s0 = m0 & (SS - 1);
    const int tid = threadIdx.x;
    const int lk = tid >> 4, lm4 = (tid & 15) << 2;
    const int warp = tid >> 5, lane = tid & 31;
    const int wm = warp & 1, wn = warp >> 1;
    const int gid = lane >> 2, tig = lane & 3;

    float4 av0, av1, bv0, bv1;
    {
        const size_t arow = ((size_t)(b * CC + lk)) * SS + s0 + lm4;
        const size_t brow = (size_t)lk * N3 + n0 + lm4;
        av0 = *(const float4*)&x[arow];
        av1 = *(const float4*)&x[arow + 64];
        bv0 = *(const float4*)&Wp[brow];
        bv1 = *(const float4*)&Wp[brow + 64];
    }
    *(float4*)&sA[0][lk][lm4]      = tf32r4(av0);
    *(float4*)&sA[0][lk][lm4 + 64] = tf32r4(av1);
    *(float4*)&sB[0][lk][lm4]      = tf32r4(bv0);
    *(float4*)&sB[0][lk][lm4 + 64] = tf32r4(bv1);
    __syncthreads();

    float acc[4][4][4] = {};

    for (int k0 = 0; k0 < CC; k0 += 16) {
        const int buf = (k0 >> 4) & 1;
        const bool more = (k0 + 16) < CC;
        if (more) {
            const size_t arow = ((size_t)(b * CC + k0 + 16 + lk)) * SS + s0 + lm4;
            const size_t brow = (size_t)(k0 + 16 + lk) * N3 + n0 + lm4;
            av0 = *(const float4*)&x[arow];
            av1 = *(const float4*)&x[arow + 64];
            bv0 = *(const float4*)&Wp[brow];
            bv1 = *(const float4*)&Wp[brow + 64];
        }
        #pragma unroll
        for (int ks = 0; ks < 16; ks += 8) {
            float afr[4][4], bfr[4][2];
            #pragma unroll
            for (int mf = 0; mf < 4; mf++) {
                const int m = wm * 64 + mf * 16 + gid;
                afr[mf][0] = sA[buf][ks + tig][m];
                afr[mf][1] = sA[buf][ks + tig][m + 8];
                afr[mf][2] = sA[buf][ks + tig + 4][m];
                afr[mf][3] = sA[buf][ks + tig + 4][m + 8];
            }
            #pragma unroll
            for (int nf = 0; nf < 4; nf++) {
                const int n = wn * 32 + nf * 8 + gid;
                bfr[nf][0] = sB[buf][ks + tig][n];
                bfr[nf][1] = sB[buf][ks + tig + 4][n];
            }
            #pragma unroll
            for (int mf = 0; mf < 4; mf++)
                #pragma unroll
                for (int nf = 0; nf < 4; nf++)
                    mma_tf32(acc[mf][nf], afr[mf], bfr[nf]);
        }
        if (more) {
            const int nb = buf ^ 1;
            *(float4*)&sA[nb][lk][lm4]      = tf32r4(av0);
            *(float4*)&sA[nb][lk][lm4 + 64] = tf32r4(av1);
            *(float4*)&sB[nb][lk][lm4]      = tf32r4(bv0);
            *(float4*)&sB[nb][lk][lm4 + 64] = tf32r4(bv1);
            __syncthreads();
        }
    }

    #pragma unroll
    for (int mf = 0; mf < 4; mf++) {
        const int rowa = m0 + wm * 64 + mf * 16 + gid;
        const int rowb = rowa + 8;
        #pragma unroll
        for (int nf = 0; nf < 4; nf++) {
            const int col = n0 + wn * 32 + nf * 8 + tig * 2;
            const float2 bias = *(const float2*)&bp[col];
            float2 oa = make_float2(acc[mf][nf][0] + bias.x, acc[mf][nf][1] + bias.y);
            float2 ob = make_float2(acc[mf][nf][2] + bias.x, acc[mf][nf][3] + bias.y);
            *(float2*)&g_qkv[(size_t)rowa * N3 + col] = oa;
            *(float2*)&g_qkv[(size_t)rowb * N3 + col] = ob;
        }
    }
}

// ---------------------------------------------------------------------------
// Kernel 2: flash attention on tf32 mma.sync.
// 128 q-tile x 64 k-tiles. 8 warps, each owns 16 q-rows x full n.
// All smem tiles natural layout, row stride 72.
// ---------------------------------------------------------------------------
__global__ __launch_bounds__(256, 2) void attn_k()
{
    extern __shared__ float sm[];
    float* sQ = sm;                 // [128][72]  (scaled, tf32)
    float* sK = sQ + 128 * STR;     // [64][72]   (tf32)
    float* sV = sK + 64 * STR;      // [64][72]   (tf32)
    float* sP = sV + 64 * STR;      // [128][72]  (tf32)

    const int bh = blockIdx.y;
    const int b = bh >> 3, h = bh & 7;
    const int q0 = blockIdx.x * 128;
    const int tid = threadIdx.x;
    const int warp = tid >> 5, lane = tid & 31;
    const int gid = lane >> 2, tig = lane & 3;
    const int qw = warp * 16;                 // this warp's q-row base

    const float* qbase = g_qkv + (size_t)b * SS * N3 + h * (3 * DH);

    // Load Q tile (128x64), scale + tf32 round, natural layout
    #pragma unroll
    for (int it = 0; it < 8; it++) {
        int idx = tid + it * 256;
        int i = idx >> 4, d4 = (idx & 15) << 2;
        float4 v = *(const float4*)&qbase[(size_t)(q0 + i) * N3 + d4];
        v.x *= ATT_SCALE; v.y *= ATT_SCALE; v.z *= ATT_SCALE; v.w *= ATT_SCALE;
        *(float4*)&sQ[i * STR + d4] = tf32r4(v);
    }

    float m_i0 = -1e30f, m_i1 = -1e30f, l_i0 = 0.f, l_i1 = 0.f;
    float o[8][4] = {};

    // Prefetch kt=0 K/V
    float4 kreg[4], vreg[4];
    #pragma unroll
    for (int it = 0; it < 4; it++) {
        int idx = tid + it * 256;
        int j = idx >> 4, c4 = (idx & 15) << 2;
        const float* row = &qbase[(size_t)j * N3];
        kreg[it] = *(const float4*)&row[DH + c4];
        vreg[it] = *(const float4*)&row[2 * DH + c4];
    }

    for (int kt = 0; kt < 16; kt++) {
        __syncthreads();   // prev tile's reads of sK/sV done (Q store @kt0)
        #pragma unroll
        for (int it = 0; it < 4; it++) {
            int idx = tid + it * 256;
            int j = idx >> 4, c4 = (idx & 15) << 2;
            *(float4*)&sK[j * STR + c4] = tf32r4(kreg[it]);
            *(float4*)&sV[j * STR + c4] = tf32r4(vreg[it]);
        }
        __syncthreads();

        if (kt + 1 < 16) {
            const int k0n = (kt + 1) * 64;
            #pragma unroll
            for (int it = 0; it < 4; it++) {
                int idx = tid + it * 256;
                int j = idx >> 4, c4 = (idx & 15) << 2;
                const float* row = &qbase[(size_t)(k0n + j) * N3];
                kreg[it] = *(const float4*)&row[DH + c4];
                vreg[it] = *(const float4*)&row[2 * DH + c4];
            }
        }

        // ---- S = Q K^T : per warp 16 rows x 64 cols ----
        float sf[8][4] = {};
        #pragma unroll
        for (int ks = 0; ks < 64; ks += 8) {
            float afr[4];
            afr[0] = sQ[(qw + gid) * STR + ks + tig];
            afr[1] = sQ[(qw + gid + 8) * STR + ks + tig];
            afr[2] = sQ[(qw + gid) * STR + ks + tig + 4];
            afr[3] = sQ[(qw + gid + 8) * STR + ks + tig + 4];
            #pragma unroll
            for (int nf = 0; nf < 8; nf++) {
                float bfr[2];
                // B[k=d][n=j] = K^T -> read natural sK transposed
                bfr[0] = sK[(nf * 8 + gid) * STR + ks + tig];
                bfr[1] = sK[(nf * 8 + gid) * STR + ks + tig + 4];
                mma_tf32(sf[nf], afr, bfr);
            }
        }

        // ---- online softmax: this thread owns rows qw+gid, qw+gid+8 ----
        {
            float mx0 = -1e30f, mx1 = -1e30f;
            #pragma unroll
            for (int nf = 0; nf < 8; nf++) {
                mx0 = fmaxf(mx0, fmaxf(sf[nf][0], sf[nf][1]));
                mx1 = fmaxf(mx1, fmaxf(sf[nf][2], sf[nf][3]));
            }
            mx0 = fmaxf(mx0, __shfl_xor_sync(0xffffffffu, mx0, 1));
            mx0 = fmaxf(mx0, __shfl_xor_sync(0xffffffffu, mx0, 2));
            mx1 = fmaxf(mx1, __shfl_xor_sync(0xffffffffu, mx1, 1));
            mx1 = fmaxf(mx1, __shfl_xor_sync(0xffffffffu, mx1, 2));
            float mn0 = fmaxf(m_i0, mx0);
            float mn1 = fmaxf(m_i1, mx1);
            float rs0 = 0.f, rs1 = 0.f;
            float* p0 = &sP[(qw + gid) * STR + 2 * tig];
            float* p1 = &sP[(qw + gid + 8) * STR + 2 * tig];
            #pragma unroll
            for (int nf = 0; nf < 8; nf++) {
                float e00 = __expf(sf[nf][0] - mn0);
                float e01 = __expf(sf[nf][1] - mn0);
                float e10 = __expf(sf[nf][2] - mn1);
                float e11 = __expf(sf[nf][3] - mn1);
                rs0 += e00 + e01;
                rs1 += e10 + e11;
                *(float2*)&p0[nf * 8] = make_float2(tf32r(e00), tf32r(e01));
                *(float2*)&p1[nf * 8] = make_float2(tf32r(e10), tf32r(e11));
            }
            rs0 += __shfl_xor_sync(0xffffffffu, rs0, 1);
            rs0 += __shfl_xor_sync(0xffffffffu, rs0, 2);
            rs1 += __shfl_xor_sync(0xffffffffu, rs1, 1);
            rs1 += __shfl_xor_sync(0xffffffffu, rs1, 2);
            float a0 = __expf(m_i0 - mn0);
            float a1 = __expf(m_i1 - mn1);
            l_i0 = l_i0 * a0 + rs0;  m_i0 = mn0;
            l_i1 = l_i1 * a1 + rs1;  m_i1 = mn1;
            #pragma unroll
            for (int nf = 0; nf < 8; nf++) {
                o[nf][0] *= a0; o[nf][1] *= a0;
                o[nf][2] *= a1; o[nf][3] *= a1;
            }
        }
        __syncwarp();   // sP rows produced/consumed within this warp

        // ---- O += P V : A-frag from sP, B-frag from natural sV ----
        #pragma unroll
        for (int ks = 0; ks < 64; ks += 8) {
            float afr[4];
            afr[0] = sP[(qw + gid) * STR + ks + tig];
            afr[1] = sP[(qw + gid + 8) * STR + ks + tig];
            afr[2] = sP[(qw + gid) * STR + ks + tig + 4];
            afr[3] = sP[(qw + gid + 8) * STR + ks + tig + 4];
            #pragma unroll
            for (int nf = 0; nf < 8; nf++) {
                float bfr[2];
                bfr[0] = sV[(ks + tig) * STR + nf * 8 + gid];
                bfr[1] = sV[(ks + tig + 4) * STR + nf * 8 + gid];
                mma_tf32(o[nf], afr, bfr);
            }
        }
    }

    const float inv0 = 1.f / l_i0;
    const float inv1 = 1.f / l_i1;
    float* rbase = g_res + ((size_t)b * SS + q0) * INNER + h * DH;
    #pragma unroll
    for (int nf = 0; nf < 8; nf++) {
        const int col = nf * 8 + 2 * tig;
        *(float2*)&rbase[(size_t)(qw + gid) * INNER + col] =
            make_float2(o[nf][0] * inv0, o[nf][1] * inv0);
        *(float2*)&rbase[(size_t)(qw + gid + 8) * INNER + col] =
            make_float2(o[nf][2] * inv1, o[nf][3] * inv1);
    }
}

// ---------------------------------------------------------------------------
// Kernel 3: out = res @ W_out + b_out + x (tf32 mma.sync, unchanged from R6)
// ---------------------------------------------------------------------------
__global__ __launch_bounds__(256, 2) void out_gemm_k(
    const float* __restrict__ x, const float* __restrict__ Wo,
    const float* __restrict__ bo, float* __restrict__ out)
{
    __shared__ float sA[2][16][132];
    __shared__ float sB[2][16][132];
    const int s0 = blockIdx.x * 128;
    const int c0 = blockIdx.y * 128;
    const int b  = blockIdx.z;
    const int tid = threadIdx.x;
    const int lk = tid >> 4, lc4 = (tid & 15) << 2;
    const int ls = tid >> 1, lkb = (tid & 1) << 3;
    const int warp = tid >> 5, lane = tid & 31;
    const int wm = warp & 1, wn = warp >> 1;
    const int gid = lane >> 2, tig = lane & 3;

    float4 av0, av1, bv0, bv1;
    {
        const size_t arow = (size_t)lk * CC + c0 + lc4;
        av0 = *(const float4*)&Wo[arow];
        av1 = *(const float4*)&Wo[arow + 64];
        const size_t brow = ((size_t)(b * SS + s0 + ls)) * INNER + lkb;
        bv0 = *(const float4*)&g_res[brow];
        bv1 = *(const float4*)&g_res[brow + 4];
    }
    *(float4*)&sA[0][lk][lc4]      = tf32r4(av0);
    *(float4*)&sA[0][lk][lc4 + 64] = tf32r4(av1);
    sB[0][lkb + 0][ls] = tf32r(bv0.x); sB[0][lkb + 1][ls] = tf32r(bv0.y);
    sB[0][lkb + 2][ls] = tf32r(bv0.z); sB[0][lkb + 3][ls] = tf32r(bv0.w);
    sB[0][lkb + 4][ls] = tf32r(bv1.x); sB[0][lkb + 5][ls] = tf32r(bv1.y);
    sB[0][lkb + 6][ls] = tf32r(bv1.z); sB[0][lkb + 7][ls] = tf32r(bv1.w);
    __syncthreads();

    float acc[4][4][4] = {};

    for (int k0 = 0; k0 < INNER; k0 += 16) {
        const int buf = (k0 >> 4) & 1;
        const bool more = (k0 + 16) < INNER;
        if (more) {
            const size_t arow = (size_t)(k0 + 16 + lk) * CC + c0 + lc4;
            av0 = *(const float4*)&Wo[arow];
            av1 = *(const float4*)&Wo[arow + 64];
            const size_t brow = ((size_t)(b * SS + s0 + ls)) * INNER + k0 + 16 + lkb;
            bv0 = *(const float4*)&g_res[brow];
            bv1 = *(const float4*)&g_res[brow + 4];
        }
        #pragma unroll
        for (int ks = 0; ks < 16; ks += 8) {
            float afr[4][4], bfr[4][2];
            #pragma unroll
            for (int mf = 0; mf < 4; mf++) {
                const int m = wm * 64 + mf * 16 + gid;
                afr[mf][0] = sA[buf][ks + tig][m];
                afr[mf][1] = sA[buf][ks + tig][m + 8];
                afr[mf][2] = sA[buf][ks + tig + 4][m];
                afr[mf][3] = sA[buf][ks + tig + 4][m + 8];
            }
            #pragma unroll
            for (int nf = 0; nf < 4; nf++) {
                const int n = wn * 32 + nf * 8 + gid;
                bfr[nf][0] = sB[buf][ks + tig][n];
                bfr[nf][1] = sB[buf][ks + tig + 4][n];
            }
            #pragma unroll
            for (int mf = 0; mf < 4; mf++)
                #pragma unroll
                for (int nf = 0; nf < 4; nf++)
                    mma_tf32(acc[mf][nf], afr[mf], bfr[nf]);
        }
        if (more) {
            const int nb = buf ^ 1;
            *(float4*)&sA[nb][lk][lc4]      = tf32r4(av0);
            *(float4*)&sA[nb][lk][lc4 + 64] = tf32r4(av1);
            sB[nb][lkb + 0][ls] = tf32r(bv0.x); sB[nb][lkb + 1][ls] = tf32r(bv0.y);
            sB[nb][lkb + 2][ls] = tf32r(bv0.z); sB[nb][lkb + 3][ls] = tf32r(bv0.w);
            sB[nb][lkb + 4][ls] = tf32r(bv1.x); sB[nb][lkb + 5][ls] = tf32r(bv1.y);
            sB[nb][lkb + 6][ls] = tf32r(bv1.z); sB[nb][lkb + 7][ls] = tf32r(bv1.w);
            __syncthreads();
        }
    }

    #pragma unroll
    for (int mf = 0; mf < 4; mf++) {
        const int ca = c0 + wm * 64 + mf * 16 + gid;
        const int cb = ca + 8;
        const float biasa = bo[ca];
        const float biasb = bo[cb];
        #pragma unroll
        for (int nf = 0; nf < 4; nf++) {
            const int s = s0 + wn * 32 + nf * 8 + tig * 2;
            const size_t basea = ((size_t)(b * CC + ca)) * SS + s;
            const size_t baseb = ((size_t)(b * CC + cb)) * SS + s;
            float2 xva = *(const float2*)&x[basea];
            float2 xvb = *(const float2*)&x[baseb];
            float2 oa = make_float2(acc[mf][nf][0] + biasa + xva.x,
                                    acc[mf][nf][1] + biasa + xva.y);
            float2 ob = make_float2(acc[mf][nf][2] + biasb + xvb.x,
                                    acc[mf][nf][3] + biasb + xvb.y);
            *(float2*)&out[basea] = oa;
            *(float2*)&out[baseb] = ob;
        }
    }
}

// ---------------------------------------------------------------------------
extern "C" void kernel_launch(void* const* d_in, const int* in_sizes, int n_in,
                              void* d_out, int out_size)
{
    const float* x  = (const float*)d_in[0];
    const float* Wp = (const float*)d_in[1];
    const float* bp = (const float*)d_in[2];
    const float* Wo = (const float*)d_in[3];
    const float* bo = (const float*)d_in[4];
    float* out = (float*)d_out;

    const int attn_smem = (128 + 64 + 64 + 128) * STR * (int)sizeof(float); // 110592
    cudaFuncSetAttribute(attn_k, cudaFuncAttributeMaxDynamicSharedMemorySize,
                         attn_smem);

    dim3 g1(N3 / 128, (BB * SS) / 128);        // 12 x 128
    qkv_gemm_k<<<g1, 256>>>(x, Wp, bp);

    dim3 g2(SS / 128, BB * HEADS);             // 8 x 128
    attn_k<<<g2, 256, attn_smem>>>();

    dim3 g3(SS / 128, CC / 128, BB);           // 8 x 4 x 16
    out_gemm_k<<<g3, 256>>>(x, Wo, bo, out);
}

// round 9
// speedup vs baseline: 1.8992x; 1.0800x over previous
#include <cuda_runtime.h>

#define BB     16
#define CC     512
#define SS     1024
#define HEADS  8
#define DH     64
#define INNER  512     // HEADS*DH
#define N3     1536    // 3*INNER
#define ATT_SCALE 0.125f  // 64^-0.5
#define STR    72      // attn smem row stride (72 mod 32 == 8)

// Scratch (static device globals — allocation-free per harness rules)
__device__ float g_qkv[(size_t)BB * SS * N3];    // [b][s][h*192 + {q,k,v}]
__device__ float g_res[(size_t)BB * SS * INNER]; // [b][s][h*64+d]

// tf32 round-to-nearest (keeps value in a float container)
__device__ __forceinline__ float tf32r(float f) {
    unsigned u;
    asm("cvt.rna.tf32.f32 %0, %1;" : "=r"(u) : "f"(f));
    return __uint_as_float(u);
}
__device__ __forceinline__ float4 tf32r4(float4 v) {
    return make_float4(tf32r(v.x), tf32r(v.y), tf32r(v.z), tf32r(v.w));
}

// m16n8k8 tf32 MMA, fp32 accumulate (D == C)
__device__ __forceinline__ void mma_tf32(float* d, const float* a, const float* b) {
    asm volatile(
        "mma.sync.aligned.m16n8k8.row.col.f32.tf32.tf32.f32 "
        "{%0,%1,%2,%3}, {%4,%5,%6,%7}, {%8,%9}, {%0,%1,%2,%3};\n"
        : "+f"(d[0]), "+f"(d[1]), "+f"(d[2]), "+f"(d[3])
        : "r"(__float_as_uint(a[0])), "r"(__float_as_uint(a[1])),
          "r"(__float_as_uint(a[2])), "r"(__float_as_uint(a[3])),
          "r"(__float_as_uint(b[0])), "r"(__float_as_uint(b[1])));
}

// ---- fragment-permuted smem layouts (k-range 16, padded groups) ----
// A element (k 0..15, m 0..127) -> group (k>>3)*8 + (m>>4), size 136 floats,
// inner: lane = (m&7)*4 + (k&3), slot = ((k>>2)&1)*2 + ((m>>3)&1)
#define AGSZ 136
#define BGSZ 72
__device__ __forceinline__ int idxA(int k, int m) {
    return (((k >> 3) * 8) + (m >> 4)) * AGSZ
         + (((m & 7) << 2) + (k & 3)) * 4 + (((k >> 2) & 1) << 1) + ((m >> 3) & 1);
}
// B element (k 0..15, n 0..127) -> group (k>>3)*16 + (n>>3), size 72 floats
__device__ __forceinline__ int idxB(int k, int n) {
    return (((k >> 3) * 16) + (n >> 3)) * BGSZ
         + ((((n & 7) << 2) + (k & 3)) << 1) + ((k >> 2) & 1);
}

// ---------------------------------------------------------------------------
// Kernel 1: qkv = xs @ W_proj + b_proj, tf32 mma.sync, frag-permuted smem.
// ---------------------------------------------------------------------------
__global__ __launch_bounds__(256, 2) void qkv_gemm_k(
    const float* __restrict__ x, const float* __restrict__ Wp,
    const float* __restrict__ bp)
{
    __shared__ float sAp[2][16 * AGSZ];   // 2176 floats each
    __shared__ float sBp[2][32 * BGSZ];   // 2304 floats each
    const int n0 = blockIdx.x * 128;
    const int m0 = blockIdx.y * 128;
    const int b  = m0 >> 10;
    const int s0 = m0 & (SS - 1);
    const int tid = threadIdx.x;
    const int lk = tid >> 4, lm4 = (tid & 15) << 2;
    const int warp = tid >> 5, lane = tid & 31;
    const int wm = warp & 1, wn = warp >> 1;
    const int gid = lane >> 2, tig = lane & 3;

    float4 av0, av1, bv0, bv1;
    {
        const size_t arow = ((size_t)(b * CC + lk)) * SS + s0 + lm4;
        const size_t brow = (size_t)lk * N3 + n0 + lm4;
        av0 = *(const float4*)&x[arow];
        av1 = *(const float4*)&x[arow + 64];
        bv0 = *(const float4*)&Wp[brow];
        bv1 = *(const float4*)&Wp[brow + 64];
    }
    {
        float a0[4] = {av0.x, av0.y, av0.z, av0.w};
        float a1[4] = {av1.x, av1.y, av1.z, av1.w};
        float b0[4] = {bv0.x, bv0.y, bv0.z, bv0.w};
        float b1[4] = {bv1.x, bv1.y, bv1.z, bv1.w};
        #pragma unroll
        for (int j = 0; j < 4; j++) {
            sAp[0][idxA(lk, lm4 + j)]      = tf32r(a0[j]);
            sAp[0][idxA(lk, lm4 + 64 + j)] = tf32r(a1[j]);
            sBp[0][idxB(lk, lm4 + j)]      = tf32r(b0[j]);
            sBp[0][idxB(lk, lm4 + 64 + j)] = tf32r(b1[j]);
        }
    }
    __syncthreads();

    float acc[4][4][4] = {};

    for (int k0 = 0; k0 < CC; k0 += 16) {
        const int buf = (k0 >> 4) & 1;
        const bool more = (k0 + 16) < CC;
        if (more) {
            const size_t arow = ((size_t)(b * CC + k0 + 16 + lk)) * SS + s0 + lm4;
            const size_t brow = (size_t)(k0 + 16 + lk) * N3 + n0 + lm4;
            av0 = *(const float4*)&x[arow];
            av1 = *(const float4*)&x[arow + 64];
            bv0 = *(const float4*)&Wp[brow];
            bv1 = *(const float4*)&Wp[brow + 64];
        }
        #pragma unroll
        for (int ks8 = 0; ks8 < 2; ks8++) {
            float4 afr[4];
            float2 bfr[4];
            #pragma unroll
            for (int mf = 0; mf < 4; mf++)
                afr[mf] = *(const float4*)&sAp[buf][(ks8 * 8 + wm * 4 + mf) * AGSZ + lane * 4];
            #pragma unroll
            for (int nf = 0; nf < 4; nf++)
                bfr[nf] = *(const float2*)&sBp[buf][(ks8 * 16 + wn * 4 + nf) * BGSZ + lane * 2];
            #pragma unroll
            for (int mf = 0; mf < 4; mf++)
                #pragma unroll
                for (int nf = 0; nf < 4; nf++)
                    mma_tf32(acc[mf][nf], (const float*)&afr[mf], (const float*)&bfr[nf]);
        }
        if (more) {
            const int nb = buf ^ 1;
            float a0[4] = {av0.x, av0.y, av0.z, av0.w};
            float a1[4] = {av1.x, av1.y, av1.z, av1.w};
            float b0[4] = {bv0.x, bv0.y, bv0.z, bv0.w};
            float b1[4] = {bv1.x, bv1.y, bv1.z, bv1.w};
            #pragma unroll
            for (int j = 0; j < 4; j++) {
                sAp[nb][idxA(lk, lm4 + j)]      = tf32r(a0[j]);
                sAp[nb][idxA(lk, lm4 + 64 + j)] = tf32r(a1[j]);
                sBp[nb][idxB(lk, lm4 + j)]      = tf32r(b0[j]);
                sBp[nb][idxB(lk, lm4 + 64 + j)] = tf32r(b1[j]);
            }
            __syncthreads();
        }
    }

    #pragma unroll
    for (int mf = 0; mf < 4; mf++) {
        const int rowa = m0 + wm * 64 + mf * 16 + gid;
        const int rowb = rowa + 8;
        #pragma unroll
        for (int nf = 0; nf < 4; nf++) {
            const int col = n0 + wn * 32 + nf * 8 + tig * 2;
            const float2 bias = *(const float2*)&bp[col];
            float2 oa = make_float2(acc[mf][nf][0] + bias.x, acc[mf][nf][1] + bias.y);
            float2 ob = make_float2(acc[mf][nf][2] + bias.x, acc[mf][nf][3] + bias.y);
            *(float2*)&g_qkv[(size_t)rowa * N3 + col] = oa;
            *(float2*)&g_qkv[(size_t)rowb * N3 + col] = ob;
        }
    }
}

// ---------------------------------------------------------------------------
// Kernel 2: flash attention on tf32 mma.sync (unchanged from R8).
// ---------------------------------------------------------------------------
__global__ __launch_bounds__(256, 2) void attn_k()
{
    extern __shared__ float sm[];
    float* sQ = sm;                 // [128][72]  (scaled, tf32)
    float* sK = sQ + 128 * STR;     // [64][72]   (tf32)
    float* sV = sK + 64 * STR;      // [64][72]   (tf32)
    float* sP = sV + 64 * STR;      // [128][72]  (tf32)

    const int bh = blockIdx.y;
    const int b = bh >> 3, h = bh & 7;
    const int q0 = blockIdx.x * 128;
    const int tid = threadIdx.x;
    const int warp = tid >> 5, lane = tid & 31;
    const int gid = lane >> 2, tig = lane & 3;
    const int qw = warp * 16;

    const float* qbase = g_qkv + (size_t)b * SS * N3 + h * (3 * DH);

    #pragma unroll
    for (int it = 0; it < 8; it++) {
        int idx = tid + it * 256;
        int i = idx >> 4, d4 = (idx & 15) << 2;
        float4 v = *(const float4*)&qbase[(size_t)(q0 + i) * N3 + d4];
        v.x *= ATT_SCALE; v.y *= ATT_SCALE; v.z *= ATT_SCALE; v.w *= ATT_SCALE;
        *(float4*)&sQ[i * STR + d4] = tf32r4(v);
    }

    float m_i0 = -1e30f, m_i1 = -1e30f, l_i0 = 0.f, l_i1 = 0.f;
    float o[8][4] = {};

    float4 kreg[4], vreg[4];
    #pragma unroll
    for (int it = 0; it < 4; it++) {
        int idx = tid + it * 256;
        int j = idx >> 4, c4 = (idx & 15) << 2;
        const float* row = &qbase[(size_t)j * N3];
        kreg[it] = *(const float4*)&row[DH + c4];
        vreg[it] = *(const float4*)&row[2 * DH + c4];
    }

    for (int kt = 0; kt < 16; kt++) {
        __syncthreads();
        #pragma unroll
        for (int it = 0; it < 4; it++) {
            int idx = tid + it * 256;
            int j = idx >> 4, c4 = (idx & 15) << 2;
            *(float4*)&sK[j * STR + c4] = tf32r4(kreg[it]);
            *(float4*)&sV[j * STR + c4] = tf32r4(vreg[it]);
        }
        __syncthreads();

        if (kt + 1 < 16) {
            const int k0n = (kt + 1) * 64;
            #pragma unroll
            for (int it = 0; it < 4; it++) {
                int idx = tid + it * 256;
                int j = idx >> 4, c4 = (idx & 15) << 2;
                const float* row = &qbase[(size_t)(k0n + j) * N3];
                kreg[it] = *(const float4*)&row[DH + c4];
                vreg[it] = *(const float4*)&row[2 * DH + c4];
            }
        }

        float sf[8][4] = {};
        #pragma unroll
        for (int ks = 0; ks < 64; ks += 8) {
            float afr[4];
            afr[0] = sQ[(qw + gid) * STR + ks + tig];
            afr[1] = sQ[(qw + gid + 8) * STR + ks + tig];
            afr[2] = sQ[(qw + gid) * STR + ks + tig + 4];
            afr[3] = sQ[(qw + gid + 8) * STR + ks + tig + 4];
            #pragma unroll
            for (int nf = 0; nf < 8; nf++) {
                float bfr[2];
                bfr[0] = sK[(nf * 8 + gid) * STR + ks + tig];
                bfr[1] = sK[(nf * 8 + gid) * STR + ks + tig + 4];
                mma_tf32(sf[nf], afr, bfr);
            }
        }

        {
            float mx0 = -1e30f, mx1 = -1e30f;
            #pragma unroll
            for (int nf = 0; nf < 8; nf++) {
                mx0 = fmaxf(mx0, fmaxf(sf[nf][0], sf[nf][1]));
                mx1 = fmaxf(mx1, fmaxf(sf[nf][2], sf[nf][3]));
            }
            mx0 = fmaxf(mx0, __shfl_xor_sync(0xffffffffu, mx0, 1));
            mx0 = fmaxf(mx0, __shfl_xor_sync(0xffffffffu, mx0, 2));
            mx1 = fmaxf(mx1, __shfl_xor_sync(0xffffffffu, mx1, 1));
            mx1 = fmaxf(mx1, __shfl_xor_sync(0xffffffffu, mx1, 2));
            float mn0 = fmaxf(m_i0, mx0);
            float mn1 = fmaxf(m_i1, mx1);
            float rs0 = 0.f, rs1 = 0.f;
            float* p0 = &sP[(qw + gid) * STR + 2 * tig];
            float* p1 = &sP[(qw + gid + 8) * STR + 2 * tig];
            #pragma unroll
            for (int nf = 0; nf < 8; nf++) {
                float e00 = __expf(sf[nf][0] - mn0);
                float e01 = __expf(sf[nf][1] - mn0);
                float e10 = __expf(sf[nf][2] - mn1);
                float e11 = __expf(sf[nf][3] - mn1);
                rs0 += e00 + e01;
                rs1 += e10 + e11;
                *(float2*)&p0[nf * 8] = make_float2(tf32r(e00), tf32r(e01));
                *(float2*)&p1[nf * 8] = make_float2(tf32r(e10), tf32r(e11));
            }
            rs0 += __shfl_xor_sync(0xffffffffu, rs0, 1);
            rs0 += __shfl_xor_sync(0xffffffffu, rs0, 2);
            rs1 += __shfl_xor_sync(0xffffffffu, rs1, 1);
            rs1 += __shfl_xor_sync(0xffffffffu, rs1, 2);
            float a0 = __expf(m_i0 - mn0);
            float a1 = __expf(m_i1 - mn1);
            l_i0 = l_i0 * a0 + rs0;  m_i0 = mn0;
            l_i1 = l_i1 * a1 + rs1;  m_i1 = mn1;
            #pragma unroll
            for (int nf = 0; nf < 8; nf++) {
                o[nf][0] *= a0; o[nf][1] *= a0;
                o[nf][2] *= a1; o[nf][3] *= a1;
            }
        }
        __syncwarp();

        #pragma unroll
        for (int ks = 0; ks < 64; ks += 8) {
            float afr[4];
            afr[0] = sP[(qw + gid) * STR + ks + tig];
            afr[1] = sP[(qw + gid + 8) * STR + ks + tig];
            afr[2] = sP[(qw + gid) * STR + ks + tig + 4];
            afr[3] = sP[(qw + gid + 8) * STR + ks + tig + 4];
            #pragma unroll
            for (int nf = 0; nf < 8; nf++) {
                float bfr[2];
                bfr[0] = sV[(ks + tig) * STR + nf * 8 + gid];
                bfr[1] = sV[(ks + tig + 4) * STR + nf * 8 + gid];
                mma_tf32(o[nf], afr, bfr);
            }
        }
    }

    const float inv0 = 1.f / l_i0;
    const float inv1 = 1.f / l_i1;
    float* rbase = g_res + ((size_t)b * SS + q0) * INNER + h * DH;
    #pragma unroll
    for (int nf = 0; nf < 8; nf++) {
        const int col = nf * 8 + 2 * tig;
        *(float2*)&rbase[(size_t)(qw + gid) * INNER + col] =
            make_float2(o[nf][0] * inv0, o[nf][1] * inv0);
        *(float2*)&rbase[(size_t)(qw + gid + 8) * INNER + col] =
            make_float2(o[nf][2] * inv1, o[nf][3] * inv1);
    }
}

// ---------------------------------------------------------------------------
// Kernel 3: out = res @ W_out + b_out + x, tf32 mma.sync, frag-permuted smem.
// ---------------------------------------------------------------------------
__global__ __launch_bounds__(256, 2) void out_gemm_k(
    const float* __restrict__ x, const float* __restrict__ Wo,
    const float* __restrict__ bo, float* __restrict__ out)
{
    __shared__ float sAp[2][16 * AGSZ];
    __shared__ float sBp[2][32 * BGSZ];
    const int s0 = blockIdx.x * 128;
    const int c0 = blockIdx.y * 128;
    const int b  = blockIdx.z;
    const int tid = threadIdx.x;
    const int lk = tid >> 4, lc4 = (tid & 15) << 2;
    const int ls = tid >> 1, lkb = (tid & 1) << 3;
    const int warp = tid >> 5, lane = tid & 31;
    const int wm = warp & 1, wn = warp >> 1;
    const int gid = lane >> 2, tig = lane & 3;

    float4 av0, av1, bv0, bv1;
    {
        const size_t arow = (size_t)lk * CC + c0 + lc4;
        av0 = *(const float4*)&Wo[arow];
        av1 = *(const float4*)&Wo[arow + 64];
        const size_t brow = ((size_t)(b * SS + s0 + ls)) * INNER + lkb;
        bv0 = *(const float4*)&g_res[brow];
        bv1 = *(const float4*)&g_res[brow + 4];
    }
    {
        float a0[4] = {av0.x, av0.y, av0.z, av0.w};
        float a1[4] = {av1.x, av1.y, av1.z, av1.w};
        float b0[4] = {bv0.x, bv0.y, bv0.z, bv0.w};
        float b1[4] = {bv1.x, bv1.y, bv1.z, bv1.w};
        #pragma unroll
        for (int j = 0; j < 4; j++) {
            sAp[0][idxA(lk, lc4 + j)]      = tf32r(a0[j]);
            sAp[0][idxA(lk, lc4 + 64 + j)] = tf32r(a1[j]);
            sBp[0][idxB(lkb + j, ls)]      = tf32r(b0[j]);
            sBp[0][idxB(lkb + 4 + j, ls)]  = tf32r(b1[j]);
        }
    }
    __syncthreads();

    float acc[4][4][4] = {};

    for (int k0 = 0; k0 < INNER; k0 += 16) {
        const int buf = (k0 >> 4) & 1;
        const bool more = (k0 + 16) < INNER;
        if (more) {
            const size_t arow = (size_t)(k0 + 16 + lk) * CC + c0 + lc4;
            av0 = *(const float4*)&Wo[arow];
            av1 = *(const float4*)&Wo[arow + 64];
            const size_t brow = ((size_t)(b * SS + s0 + ls)) * INNER + k0 + 16 + lkb;
            bv0 = *(const float4*)&g_res[brow];
            bv1 = *(const float4*)&g_res[brow + 4];
        }
        #pragma unroll
        for (int ks8 = 0; ks8 < 2; ks8++) {
            float4 afr[4];
            float2 bfr[4];
            #pragma unroll
            for (int mf = 0; mf < 4; mf++)
                afr[mf] = *(const float4*)&sAp[buf][(ks8 * 8 + wm * 4 + mf) * AGSZ + lane * 4];
            #pragma unroll
            for (int nf = 0; nf < 4; nf++)
                bfr[nf] = *(const float2*)&sBp[buf][(ks8 * 16 + wn * 4 + nf) * BGSZ + lane * 2];
            #pragma unroll
            for (int mf = 0; mf < 4; mf++)
                #pragma unroll
                for (int nf = 0; nf < 4; nf++)
                    mma_tf32(acc[mf][nf], (const float*)&afr[mf], (const float*)&bfr[nf]);
        }
        if (more) {
            const int nb = buf ^ 1;
            float a0[4] = {av0.x, av0.y, av0.z, av0.w};
            float a1[4] = {av1.x, av1.y, av1.z, av1.w};
            float b0[4] = {bv0.x, bv0.y, bv0.z, bv0.w};
            float b1[4] = {bv1.x, bv1.y, bv1.z, bv1.w};
            #pragma unroll
            for (int j = 0; j < 4; j++) {
                sAp[nb][idxA(lk, lc4 + j)]      = tf32r(a0[j]);
                sAp[nb][idxA(lk, lc4 + 64 + j)] = tf32r(a1[j]);
                sBp[nb][idxB(lkb + j, ls)]      = tf32r(b0[j]);
                sBp[nb][idxB(lkb + 4 + j, ls)]  = tf32r(b1[j]);
            }
            __syncthreads();
        }
    }

    #pragma unroll
    for (int mf = 0; mf < 4; mf++) {
        const int ca = c0 + wm * 64 + mf * 16 + gid;
        const int cb = ca + 8;
        const float biasa = bo[ca];
        const float biasb = bo[cb];
        #pragma unroll
        for (int nf = 0; nf < 4; nf++) {
            const int s = s0 + wn * 32 + nf * 8 + tig * 2;
            const size_t basea = ((size_t)(b * CC + ca)) * SS + s;
            const size_t baseb = ((size_t)(b * CC + cb)) * SS + s;
            float2 xva = *(const float2*)&x[basea];
            float2 xvb = *(const float2*)&x[baseb];
            float2 oa = make_float2(acc[mf][nf][0] + biasa + xva.x,
                                    acc[mf][nf][1] + biasa + xva.y);
            float2 ob = make_float2(acc[mf][nf][2] + biasb + xvb.x,
                                    acc[mf][nf][3] + biasb + xvb.y);
            *(float2*)&out[basea] = oa;
            *(float2*)&out[baseb] = ob;
        }
    }
}

// ---------------------------------------------------------------------------
extern "C" void kernel_launch(void* const* d_in, const int* in_sizes, int n_in,
                              void* d_out, int out_size)
{
    const float* x  = (const float*)d_in[0];
    const float* Wp = (const float*)d_in[1];
    const float* bp = (const float*)d_in[2];
    const float* Wo = (const float*)d_in[3];
    const float* bo = (const float*)d_in[4];
    float* out = (float*)d_out;

    const int attn_smem = (128 + 64 + 64 + 128) * STR * (int)sizeof(float); // 110592
    cudaFuncSetAttribute(attn_k, cudaFuncAttributeMaxDynamicSharedMemorySize,
                         attn_smem);

    dim3 g1(N3 / 128, (BB * SS) / 128);        // 12 x 128
    qkv_gemm_k<<<g1, 256>>>(x, Wp, bp);

    dim3 g2(SS / 128, BB * HEADS);             // 8 x 128
    attn_k<<<g2, 256, attn_smem>>>();

    dim3 g3(SS / 128, CC / 128, BB);           // 8 x 4 x 16
    out_gemm_k<<<g3, 256>>>(x, Wo, bo, out);
}